// round 3
// baseline (speedup 1.0000x reference)
#include <cuda_runtime.h>
#include <math.h>

#define NN 100000
#define NE 1000000
#define IN_CH 64
#define HID 128
#define NG 256

// ---------------- scratch (device globals; no allocation) ----------------
__device__ int g_idx64;              // 1 if indices are int64, 0 if int32
__device__ int g_cnt[NN];
__device__ int g_row[NN];
__device__ int g_cur[NN];
__device__ float g_invdeg[NN];
__device__ int g_srcs[NE];
__device__ __align__(16) float g_agg1[NN * IN_CH];   // 25.6 MB
__device__ __align__(16) float g_agg2[NN * HID];     // 51.2 MB
__device__ __align__(16) float g_h1[NN * HID];       // 51.2 MB
__device__ float g_pooled[NG * HID];

// index accessor honoring detected dtype
__device__ __forceinline__ int getidx(const void* p, long long i) {
    if (g_idx64) return (int)((const long long*)p)[i];
    return ((const int*)p)[i];
}

// ---------------- dtype probe ----------------
// int64 node indices < 2^32 -> high halves all zero.
// int32 data packs two indices per u64 -> high half = next index (nonzero w.h.p.)
__global__ void probe_dtype(const unsigned long long* __restrict__ ei) {
    if (threadIdx.x == 0 && blockIdx.x == 0) {
        int is64 = 1;
        for (int i = 0; i < 16; i++)
            if (ei[i] >> 32) is64 = 0;
        g_idx64 = is64;
    }
}

// ---------------- zero counters + pooled ----------------
__global__ void zero_small() {
    int i = blockIdx.x * blockDim.x + threadIdx.x;
    int stride = gridDim.x * blockDim.x;
    for (int j = i; j < NN; j += stride) g_cnt[j] = 0;
    for (int j = i; j < NG * HID; j += stride) g_pooled[j] = 0.f;
}

// ---------------- histogram of dst degrees ----------------
__global__ void __launch_bounds__(256) hist(const void* __restrict__ ei) {
    int e = blockIdx.x * blockDim.x + threadIdx.x;
    if (e >= NE) return;
    int dst = getidx(ei, NE + e);
    atomicAdd(&g_cnt[dst], 1);
}

// ---------------- exclusive scan over 100k counts (single block) ----------------
__global__ void __launch_bounds__(1024) scan_rows() {
    __shared__ int sbuf[1024];
    int t = threadIdx.x;
    const int CH = (NN + 1023) / 1024;  // 98
    int base = t * CH;
    int s = 0;
    for (int i = 0; i < CH; i++) {
        int idx = base + i;
        if (idx < NN) s += g_cnt[idx];
    }
    sbuf[t] = s;
    __syncthreads();
    for (int off = 1; off < 1024; off <<= 1) {
        int v = (t >= off) ? sbuf[t - off] : 0;
        __syncthreads();
        sbuf[t] += v;
        __syncthreads();
    }
    int run = sbuf[t] - s;  // exclusive prefix
    for (int i = 0; i < CH; i++) {
        int idx = base + i;
        if (idx >= NN) break;
        int c = g_cnt[idx];
        g_row[idx] = run;
        g_cur[idx] = run;
        g_invdeg[idx] = 1.0f / fmaxf((float)c, 1.0f);
        run += c;
    }
}

// ---------------- fill CSR src lists ----------------
__global__ void __launch_bounds__(256) fill_csr(const void* __restrict__ ei) {
    int e = blockIdx.x * blockDim.x + threadIdx.x;
    if (e >= NE) return;
    int dst = getidx(ei, NE + e);
    int src = getidx(ei, e);
    int pos = atomicAdd(&g_cur[dst], 1);
    g_srcs[pos] = src;
}

// ---------------- gather-mean layer 1: agg1[n] = mean_{s in N(n)} x[s]  (64 ch) ----------------
__global__ void __launch_bounds__(256) gather1(const float4* __restrict__ x4) {
    unsigned t = blockIdx.x * blockDim.x + threadIdx.x;
    unsigned n = t >> 4, q = t & 15;
    if (n >= NN) return;
    int start = g_row[n];
    int cnt = g_cnt[n];
    float inv = g_invdeg[n];
    float4 acc = make_float4(0.f, 0.f, 0.f, 0.f);
    for (int j = 0; j < cnt; j++) {
        int s = g_srcs[start + j];
        float4 v = x4[(size_t)s * 16 + q];
        acc.x += v.x; acc.y += v.y; acc.z += v.z; acc.w += v.w;
    }
    acc.x *= inv; acc.y *= inv; acc.z *= inv; acc.w *= inv;
    ((float4*)g_agg1)[(size_t)n * 16 + q] = acc;
}

// ---------------- gather-mean layer 2: agg2[n] = mean_{s in N(n)} h1[s]  (128 ch) ----------------
__global__ void __launch_bounds__(256) gather2() {
    unsigned t = blockIdx.x * blockDim.x + threadIdx.x;
    unsigned n = t >> 5, q = t & 31;
    if (n >= NN) return;
    int start = g_row[n];
    int cnt = g_cnt[n];
    float inv = g_invdeg[n];
    const float4* h4 = (const float4*)g_h1;
    float4 acc = make_float4(0.f, 0.f, 0.f, 0.f);
    for (int j = 0; j < cnt; j++) {
        int s = g_srcs[start + j];
        float4 v = h4[(size_t)s * 32 + q];
        acc.x += v.x; acc.y += v.y; acc.z += v.z; acc.w += v.w;
    }
    acc.x *= inv; acc.y *= inv; acc.z *= inv; acc.w *= inv;
    ((float4*)g_agg2)[(size_t)n * 32 + q] = acc;
}

// ---------------- fused SAGE GEMM body ----------------
// out[n, c] = relu( agg[n] @ W0^T + feat[n] @ W1^T + bias )    (agg pre-normalized)
// Tile: 64 nodes x 128 channels, 256 threads, 4x8 outputs/thread.
template <int K, bool DO_POOL>
__device__ __forceinline__ void sage_gemm_body(
    const float* __restrict__ agg, const float* __restrict__ feat,
    const float* __restrict__ W0, const float* __restrict__ W1,
    const float* __restrict__ bias, float* __restrict__ out,
    const void* __restrict__ batch) {
    constexpr int KH = K / 2;
    __shared__ float As[16][64];
    __shared__ float Bs[16][128];

    int tid = threadIdx.x;
    int tx = tid & 15;   // channel group: c0 = tx*8
    int ty = tid >> 4;   // node group: m = ty*4 + i
    int m0 = blockIdx.x * 64;

    int a_node = tid >> 2;
    int a_q = tid & 3;
    int node_g = m0 + a_node;
    bool a_valid = node_g < NN;

    float acc[4][8];
#pragma unroll
    for (int i = 0; i < 4; i++)
#pragma unroll
        for (int j = 0; j < 8; j++) acc[i][j] = 0.f;

    for (int kk = 0; kk < K; kk += 16) {
        __syncthreads();
        // A tile (64 nodes x 16 k), k-major
        {
            float4 v = make_float4(0.f, 0.f, 0.f, 0.f);
            int kg = kk + a_q * 4;
            if (a_valid) {
                if (kg < KH)
                    v = *(const float4*)(agg + (size_t)node_g * KH + kg);
                else
                    v = *(const float4*)(feat + (size_t)node_g * KH + (kg - KH));
            }
            As[a_q * 4 + 0][a_node] = v.x;
            As[a_q * 4 + 1][a_node] = v.y;
            As[a_q * 4 + 2][a_node] = v.z;
            As[a_q * 4 + 3][a_node] = v.w;
        }
        // B tile (16 k x 128 ch) from row-major W [HID, KH]
#pragma unroll
        for (int j = 0; j < 2; j++) {
            int f = tid * 2 + j;      // 0..511
            int c = f >> 2, q = f & 3;
            int kg = kk + q * 4;
            const float* wsrc = (kg < KH) ? (W0 + (size_t)c * KH + kg)
                                          : (W1 + (size_t)c * KH + (kg - KH));
            float4 w = *(const float4*)wsrc;
            Bs[q * 4 + 0][c] = w.x;
            Bs[q * 4 + 1][c] = w.y;
            Bs[q * 4 + 2][c] = w.z;
            Bs[q * 4 + 3][c] = w.w;
        }
        __syncthreads();
#pragma unroll
        for (int k = 0; k < 16; k++) {
            float4 a = *(const float4*)&As[k][ty * 4];
            float4 b0 = *(const float4*)&Bs[k][tx * 8];
            float4 b1 = *(const float4*)&Bs[k][tx * 8 + 4];
            float av[4] = {a.x, a.y, a.z, a.w};
            float bv[8] = {b0.x, b0.y, b0.z, b0.w, b1.x, b1.y, b1.z, b1.w};
#pragma unroll
            for (int i = 0; i < 4; i++)
#pragma unroll
                for (int j = 0; j < 8; j++) acc[i][j] += av[i] * bv[j];
        }
    }

    int c0 = tx * 8;
    float4 bb0 = *(const float4*)(bias + c0);
    float4 bb1 = *(const float4*)(bias + c0 + 4);
    float bv[8] = {bb0.x, bb0.y, bb0.z, bb0.w, bb1.x, bb1.y, bb1.z, bb1.w};
#pragma unroll
    for (int i = 0; i < 4; i++) {
        int node = m0 + ty * 4 + i;
        if (node >= NN) break;
        float r[8];
#pragma unroll
        for (int j = 0; j < 8; j++) r[j] = fmaxf(acc[i][j] + bv[j], 0.f);
        if (DO_POOL) {
            int g = getidx(batch, node);
            float* p = g_pooled + (size_t)g * HID + c0;
#pragma unroll
            for (int j = 0; j < 8; j++) atomicAdd(p + j, r[j]);
        } else {
            float* p = out + (size_t)node * HID + c0;
            *(float4*)p = make_float4(r[0], r[1], r[2], r[3]);
            *(float4*)(p + 4) = make_float4(r[4], r[5], r[6], r[7]);
        }
    }
}

__global__ void __launch_bounds__(256) sage_gemm_l1(
    const float* __restrict__ x, const float* __restrict__ W0,
    const float* __restrict__ W1, const float* __restrict__ bias) {
    sage_gemm_body<2 * IN_CH, false>(g_agg1, x, W0, W1, bias, g_h1, nullptr);
}

__global__ void __launch_bounds__(256) sage_gemm_l2(
    const float* __restrict__ W0, const float* __restrict__ W1,
    const float* __restrict__ bias, const void* __restrict__ batch) {
    sage_gemm_body<2 * HID, true>(g_agg2, g_h1, W0, W1, bias, nullptr, batch);
}

// ---------------- finalize: per-graph mean, Wout, log_softmax ----------------
__global__ void __launch_bounds__(256) finalize(const void* __restrict__ batch,
                                                const float* __restrict__ Wout,
                                                const float* __restrict__ bout,
                                                float* __restrict__ outp) {
    int g = threadIdx.x;  // one thread per graph
    auto lower_bound = [&](int v) {
        int lo = 0, hi = NN;
        while (lo < hi) {
            int mid = (lo + hi) >> 1;
            if (getidx(batch, mid) < v) lo = mid + 1; else hi = mid;
        }
        return lo;
    };
    int cnt = lower_bound(g + 1) - lower_bound(g);
    float inv = 1.0f / fmaxf((float)cnt, 1.0f);
    float l0 = bout[0], l1 = bout[1];
    for (int c = 0; c < HID; c++) {
        float p = g_pooled[(size_t)g * HID + c] * inv;
        l0 += p * Wout[c];
        l1 += p * Wout[HID + c];
    }
    float m = fmaxf(l0, l1);
    float lse = m + logf(expf(l0 - m) + expf(l1 - m));
    outp[g * 2 + 0] = l0 - lse;
    outp[g * 2 + 1] = l1 - lse;
}

// ---------------- launch ----------------
extern "C" void kernel_launch(void* const* d_in, const int* in_sizes, int n_in,
                              void* d_out, int out_size) {
    const float* x = (const float*)d_in[0];
    const void* ei = d_in[1];
    const void* batch = d_in[2];
    const float* Wl1 = (const float*)d_in[3];
    const float* bl1 = (const float*)d_in[4];
    const float* Wr1 = (const float*)d_in[5];
    const float* Wl2 = (const float*)d_in[6];
    const float* bl2 = (const float*)d_in[7];
    const float* Wr2 = (const float*)d_in[8];
    const float* Wout = (const float*)d_in[9];
    const float* bout = (const float*)d_in[10];
    float* out = (float*)d_out;

    int eb = (NE + 255) / 256;
    int gemm_blocks = (NN + 63) / 64;

    probe_dtype<<<1, 32>>>((const unsigned long long*)ei);
    zero_small<<<256, 256>>>();
    hist<<<eb, 256>>>(ei);
    scan_rows<<<1, 1024>>>();
    fill_csr<<<eb, 256>>>(ei);

    gather1<<<(NN * 16 + 255) / 256, 256>>>((const float4*)x);
    sage_gemm_l1<<<gemm_blocks, 256>>>(x, Wl1, Wr1, bl1);
    gather2<<<(NN * 32 + 255) / 256, 256>>>();
    sage_gemm_l2<<<gemm_blocks, 256>>>(Wl2, Wr2, bl2, batch);
    finalize<<<1, 256>>>(batch, Wout, bout, out);
}

// round 5
// speedup vs baseline: 1.3662x; 1.3662x over previous
#include <cuda_runtime.h>
#include <math.h>

#define NN 100000
#define NE 1000000
#define IN_CH 64
#define HID 128
#define NG 256

#define SCAN_BLOCKS 128
#define SCAN_CH ((NN + SCAN_BLOCKS - 1) / SCAN_BLOCKS)   // 782

// ---------------- scratch (device globals; no allocation) ----------------
__device__ int g_idx64;              // 1 if indices are int64, 0 if int32
__device__ int g_cnt[NN];
__device__ int g_row[NN];
__device__ int g_cur[NN];
__device__ float g_invdeg[NN];
__device__ int g_srcs[NE];
__device__ int g_blocksum[SCAN_BLOCKS];
__device__ __align__(16) float g_agg1[NN * IN_CH];   // 25.6 MB
__device__ __align__(16) float g_agg2[NN * HID];     // 51.2 MB
__device__ __align__(16) float g_h1[NN * HID];       // 51.2 MB
__device__ float g_pooled[NG * HID];

// index accessor honoring detected dtype
__device__ __forceinline__ int getidx(const void* p, long long i) {
    if (g_idx64) return (int)((const long long*)p)[i];
    return ((const int*)p)[i];
}

// ---------------- dtype probe ----------------
__global__ void probe_dtype(const unsigned long long* __restrict__ ei) {
    if (threadIdx.x == 0 && blockIdx.x == 0) {
        int is64 = 1;
        for (int i = 0; i < 16; i++)
            if (ei[i] >> 32) is64 = 0;
        g_idx64 = is64;
    }
}

// ---------------- zero counters + pooled ----------------
__global__ void zero_small() {
    int i = blockIdx.x * blockDim.x + threadIdx.x;
    int stride = gridDim.x * blockDim.x;
    for (int j = i; j < NN; j += stride) g_cnt[j] = 0;
    for (int j = i; j < NG * HID; j += stride) g_pooled[j] = 0.f;
}

// ---------------- histogram of dst degrees ----------------
__global__ void __launch_bounds__(256) hist(const void* __restrict__ ei) {
    int e = blockIdx.x * blockDim.x + threadIdx.x;
    if (e >= NE) return;
    int dst = getidx(ei, NE + e);
    atomicAdd(&g_cnt[dst], 1);
}

// ---------------- 3-phase scan ----------------
// phase 1: per-block chunk sums (coalesced)
__global__ void __launch_bounds__(256) scan_p1() {
    __shared__ int sb[256];
    int b = blockIdx.x, t = threadIdx.x;
    int base = b * SCAN_CH;
    int end = min(base + SCAN_CH, NN);
    int s = 0;
    for (int idx = base + t; idx < end; idx += 256) s += g_cnt[idx];
    sb[t] = s;
    __syncthreads();
    for (int off = 128; off > 0; off >>= 1) {
        if (t < off) sb[t] += sb[t + off];
        __syncthreads();
    }
    if (t == 0) g_blocksum[b] = sb[0];
}

// phase 2: exclusive scan of 128 block sums (one block)
__global__ void __launch_bounds__(128) scan_p2() {
    __shared__ int sb[128];
    int t = threadIdx.x;
    int v = g_blocksum[t];
    sb[t] = v;
    __syncthreads();
    for (int off = 1; off < 128; off <<= 1) {
        int u = (t >= off) ? sb[t - off] : 0;
        __syncthreads();
        sb[t] += u;
        __syncthreads();
    }
    g_blocksum[t] = sb[t] - v;   // exclusive
}

// phase 3: per-block tiled exclusive scan, write row/cur/invdeg
__global__ void __launch_bounds__(256) scan_p3() {
    __shared__ int sb[256];
    __shared__ int s_off;
    int b = blockIdx.x, t = threadIdx.x;
    int base = b * SCAN_CH;
    int end = min(base + SCAN_CH, NN);
    if (t == 0) s_off = g_blocksum[b];
    __syncthreads();
    for (int tile = base; tile < end; tile += 256) {
        int idx = tile + t;
        int c = (idx < end) ? g_cnt[idx] : 0;
        sb[t] = c;
        __syncthreads();
        for (int off = 1; off < 256; off <<= 1) {
            int u = (t >= off) ? sb[t - off] : 0;
            __syncthreads();
            sb[t] += u;
            __syncthreads();
        }
        int incl = sb[t];
        int excl = incl - c;
        if (idx < end) {
            int r = s_off + excl;
            g_row[idx] = r;
            g_cur[idx] = r;
            g_invdeg[idx] = 1.0f / fmaxf((float)c, 1.0f);
        }
        __syncthreads();
        if (t == 255) s_off += sb[255];
        __syncthreads();
    }
}

// ---------------- fill CSR src lists ----------------
__global__ void __launch_bounds__(256) fill_csr(const void* __restrict__ ei) {
    int e = blockIdx.x * blockDim.x + threadIdx.x;
    if (e >= NE) return;
    int dst = getidx(ei, NE + e);
    int src = getidx(ei, e);
    int pos = atomicAdd(&g_cur[dst], 1);
    g_srcs[pos] = src;
}

// ---------------- gather-mean layer 1: agg1[n] = mean_{s in N(n)} x[s]  (64 ch) ----------------
__global__ void __launch_bounds__(256) gather1(const float4* __restrict__ x4) {
    unsigned t = blockIdx.x * blockDim.x + threadIdx.x;
    unsigned n = t >> 4, q = t & 15;
    if (n >= NN) return;
    int start = g_row[n];
    int cnt = g_cnt[n];
    float inv = g_invdeg[n];
    float4 acc = make_float4(0.f, 0.f, 0.f, 0.f);
    for (int j = 0; j < cnt; j++) {
        int s = g_srcs[start + j];
        float4 v = x4[(size_t)s * 16 + q];
        acc.x += v.x; acc.y += v.y; acc.z += v.z; acc.w += v.w;
    }
    acc.x *= inv; acc.y *= inv; acc.z *= inv; acc.w *= inv;
    ((float4*)g_agg1)[(size_t)n * 16 + q] = acc;
}

// ---------------- gather-mean layer 2: agg2[n] = mean_{s in N(n)} h1[s]  (128 ch) ----------------
__global__ void __launch_bounds__(256) gather2() {
    unsigned t = blockIdx.x * blockDim.x + threadIdx.x;
    unsigned n = t >> 5, q = t & 31;
    if (n >= NN) return;
    int start = g_row[n];
    int cnt = g_cnt[n];
    float inv = g_invdeg[n];
    const float4* h4 = (const float4*)g_h1;
    float4 acc = make_float4(0.f, 0.f, 0.f, 0.f);
    for (int j = 0; j < cnt; j++) {
        int s = g_srcs[start + j];
        float4 v = h4[(size_t)s * 32 + q];
        acc.x += v.x; acc.y += v.y; acc.z += v.z; acc.w += v.w;
    }
    acc.x *= inv; acc.y *= inv; acc.z *= inv; acc.w *= inv;
    ((float4*)g_agg2)[(size_t)n * 32 + q] = acc;
}

// ---------------- fused SAGE GEMM body ----------------
template <int K, bool DO_POOL>
__device__ __forceinline__ void sage_gemm_body(
    const float* __restrict__ agg, const float* __restrict__ feat,
    const float* __restrict__ W0, const float* __restrict__ W1,
    const float* __restrict__ bias, float* __restrict__ out,
    const void* __restrict__ batch) {
    constexpr int KH = K / 2;
    __shared__ float As[16][64];
    __shared__ float Bs[16][128];

    int tid = threadIdx.x;
    int tx = tid & 15;   // channel group: c0 = tx*8
    int ty = tid >> 4;   // node group: m = ty*4 + i
    int m0 = blockIdx.x * 64;

    int a_node = tid >> 2;
    int a_q = tid & 3;
    int node_g = m0 + a_node;
    bool a_valid = node_g < NN;

    float acc[4][8];
#pragma unroll
    for (int i = 0; i < 4; i++)
#pragma unroll
        for (int j = 0; j < 8; j++) acc[i][j] = 0.f;

    for (int kk = 0; kk < K; kk += 16) {
        __syncthreads();
        {
            float4 v = make_float4(0.f, 0.f, 0.f, 0.f);
            int kg = kk + a_q * 4;
            if (a_valid) {
                if (kg < KH)
                    v = *(const float4*)(agg + (size_t)node_g * KH + kg);
                else
                    v = *(const float4*)(feat + (size_t)node_g * KH + (kg - KH));
            }
            As[a_q * 4 + 0][a_node] = v.x;
            As[a_q * 4 + 1][a_node] = v.y;
            As[a_q * 4 + 2][a_node] = v.z;
            As[a_q * 4 + 3][a_node] = v.w;
        }
#pragma unroll
        for (int j = 0; j < 2; j++) {
            int f = tid * 2 + j;
            int c = f >> 2, q = f & 3;
            int kg = kk + q * 4;
            const float* wsrc = (kg < KH) ? (W0 + (size_t)c * KH + kg)
                                          : (W1 + (size_t)c * KH + (kg - KH));
            float4 w = *(const float4*)wsrc;
            Bs[q * 4 + 0][c] = w.x;
            Bs[q * 4 + 1][c] = w.y;
            Bs[q * 4 + 2][c] = w.z;
            Bs[q * 4 + 3][c] = w.w;
        }
        __syncthreads();
#pragma unroll
        for (int k = 0; k < 16; k++) {
            float4 a = *(const float4*)&As[k][ty * 4];
            float4 b0 = *(const float4*)&Bs[k][tx * 8];
            float4 b1 = *(const float4*)&Bs[k][tx * 8 + 4];
            float av[4] = {a.x, a.y, a.z, a.w};
            float bv[8] = {b0.x, b0.y, b0.z, b0.w, b1.x, b1.y, b1.z, b1.w};
#pragma unroll
            for (int i = 0; i < 4; i++)
#pragma unroll
                for (int j = 0; j < 8; j++) acc[i][j] += av[i] * bv[j];
        }
    }

    int c0 = tx * 8;
    float4 bb0 = *(const float4*)(bias + c0);
    float4 bb1 = *(const float4*)(bias + c0 + 4);
    float bv[8] = {bb0.x, bb0.y, bb0.z, bb0.w, bb1.x, bb1.y, bb1.z, bb1.w};
#pragma unroll
    for (int i = 0; i < 4; i++) {
        int node = m0 + ty * 4 + i;
        if (node >= NN) break;
        float r[8];
#pragma unroll
        for (int j = 0; j < 8; j++) r[j] = fmaxf(acc[i][j] + bv[j], 0.f);
        if (DO_POOL) {
            int g = getidx(batch, node);
            float* p = g_pooled + (size_t)g * HID + c0;
#pragma unroll
            for (int j = 0; j < 8; j++) atomicAdd(p + j, r[j]);
        } else {
            float* p = out + (size_t)node * HID + c0;
            *(float4*)p = make_float4(r[0], r[1], r[2], r[3]);
            *(float4*)(p + 4) = make_float4(r[4], r[5], r[6], r[7]);
        }
    }
}

__global__ void __launch_bounds__(256) sage_gemm_l1(
    const float* __restrict__ x, const float* __restrict__ W0,
    const float* __restrict__ W1, const float* __restrict__ bias) {
    sage_gemm_body<2 * IN_CH, false>(g_agg1, x, W0, W1, bias, g_h1, nullptr);
}

__global__ void __launch_bounds__(256) sage_gemm_l2(
    const float* __restrict__ W0, const float* __restrict__ W1,
    const float* __restrict__ bias, const void* __restrict__ batch) {
    sage_gemm_body<2 * HID, true>(g_agg2, g_h1, W0, W1, bias, nullptr, batch);
}

// ---------------- finalize: per-graph mean, Wout, log_softmax ----------------
__global__ void __launch_bounds__(256) finalize(const void* __restrict__ batch,
                                                const float* __restrict__ Wout,
                                                const float* __restrict__ bout,
                                                float* __restrict__ outp) {
    int g = threadIdx.x;
    auto lower_bound = [&](int v) {
        int lo = 0, hi = NN;
        while (lo < hi) {
            int mid = (lo + hi) >> 1;
            if (getidx(batch, mid) < v) lo = mid + 1; else hi = mid;
        }
        return lo;
    };
    int cnt = lower_bound(g + 1) - lower_bound(g);
    float inv = 1.0f / fmaxf((float)cnt, 1.0f);
    float l0 = bout[0], l1 = bout[1];
    for (int c = 0; c < HID; c++) {
        float p = g_pooled[(size_t)g * HID + c] * inv;
        l0 += p * Wout[c];
        l1 += p * Wout[HID + c];
    }
    float m = fmaxf(l0, l1);
    float lse = m + logf(expf(l0 - m) + expf(l1 - m));
    outp[g * 2 + 0] = l0 - lse;
    outp[g * 2 + 1] = l1 - lse;
}

// ---------------- launch ----------------
extern "C" void kernel_launch(void* const* d_in, const int* in_sizes, int n_in,
                              void* d_out, int out_size) {
    const float* x = (const float*)d_in[0];
    const void* ei = d_in[1];
    const void* batch = d_in[2];
    const float* Wl1 = (const float*)d_in[3];
    const float* bl1 = (const float*)d_in[4];
    const float* Wr1 = (const float*)d_in[5];
    const float* Wl2 = (const float*)d_in[6];
    const float* bl2 = (const float*)d_in[7];
    const float* Wr2 = (const float*)d_in[8];
    const float* Wout = (const float*)d_in[9];
    const float* bout = (const float*)d_in[10];
    float* out = (float*)d_out;

    int eb = (NE + 255) / 256;
    int gemm_blocks = (NN + 63) / 64;

    probe_dtype<<<1, 32>>>((const unsigned long long*)ei);
    zero_small<<<256, 256>>>();
    hist<<<eb, 256>>>(ei);
    scan_p1<<<SCAN_BLOCKS, 256>>>();
    scan_p2<<<1, 128>>>();
    scan_p3<<<SCAN_BLOCKS, 256>>>();
    fill_csr<<<eb, 256>>>(ei);

    gather1<<<(NN * 16 + 255) / 256, 256>>>((const float4*)x);
    sage_gemm_l1<<<gemm_blocks, 256>>>(x, Wl1, Wr1, bl1);
    gather2<<<(NN * 32 + 255) / 256, 256>>>();
    sage_gemm_l2<<<gemm_blocks, 256>>>(Wl2, Wr2, bl2, batch);
    finalize<<<1, 256>>>(batch, Wout, bout, out);
}

// round 6
// speedup vs baseline: 2.3830x; 1.7442x over previous
#include <cuda_runtime.h>
#include <math.h>

#define NN 100000
#define NE 1000000
#define IN_CH 64
#define HID 128
#define NG 256

#define SCAN_BLOCKS 128
#define SCAN_CH ((NN + SCAN_BLOCKS - 1) / SCAN_BLOCKS)   // 782

// ---------------- scratch (device globals; no allocation) ----------------
__device__ int g_idx64;              // 1 if indices are int64, 0 if int32
__device__ int g_cnt[NN];
__device__ int g_row[NN];
__device__ int g_cur[NN];
__device__ float g_invdeg[NN];
__device__ int g_srcs[NE];
__device__ int g_blocksum[SCAN_BLOCKS];
__device__ __align__(16) float g_agg1[NN * IN_CH];   // 25.6 MB
__device__ __align__(16) float g_agg2[NN * HID];     // 51.2 MB
__device__ __align__(16) float g_h1[NN * HID];       // 51.2 MB
__device__ float g_pooled[NG * HID];

// index accessor honoring detected dtype
__device__ __forceinline__ int getidx(const void* p, long long i) {
    if (g_idx64) return (int)((const long long*)p)[i];
    return ((const int*)p)[i];
}

// ---------------- tf32 helpers ----------------
__device__ __forceinline__ unsigned f2tf(float f) {
    unsigned u;
    asm("cvt.rna.tf32.f32 %0, %1;" : "=r"(u) : "f"(f));
    return u;
}

__device__ __forceinline__ void mma_tf32(float* c, const unsigned* a, const unsigned* b) {
    asm volatile(
        "mma.sync.aligned.m16n8k8.row.col.f32.tf32.tf32.f32 "
        "{%0,%1,%2,%3},{%4,%5,%6,%7},{%8,%9},{%0,%1,%2,%3};"
        : "+f"(c[0]), "+f"(c[1]), "+f"(c[2]), "+f"(c[3])
        : "r"(a[0]), "r"(a[1]), "r"(a[2]), "r"(a[3]), "r"(b[0]), "r"(b[1]));
}

// ---------------- dtype probe ----------------
__global__ void probe_dtype(const unsigned long long* __restrict__ ei) {
    if (threadIdx.x == 0 && blockIdx.x == 0) {
        int is64 = 1;
        for (int i = 0; i < 16; i++)
            if (ei[i] >> 32) is64 = 0;
        g_idx64 = is64;
    }
}

// ---------------- zero counters + pooled ----------------
__global__ void zero_small() {
    int i = blockIdx.x * blockDim.x + threadIdx.x;
    int stride = gridDim.x * blockDim.x;
    for (int j = i; j < NN; j += stride) g_cnt[j] = 0;
    for (int j = i; j < NG * HID; j += stride) g_pooled[j] = 0.f;
}

// ---------------- histogram of dst degrees ----------------
__global__ void __launch_bounds__(256) hist(const void* __restrict__ ei) {
    int e = blockIdx.x * blockDim.x + threadIdx.x;
    if (e >= NE) return;
    int dst = getidx(ei, NE + e);
    atomicAdd(&g_cnt[dst], 1);
}

// ---------------- 3-phase scan ----------------
__global__ void __launch_bounds__(256) scan_p1() {
    __shared__ int sb[256];
    int b = blockIdx.x, t = threadIdx.x;
    int base = b * SCAN_CH;
    int end = min(base + SCAN_CH, NN);
    int s = 0;
    for (int idx = base + t; idx < end; idx += 256) s += g_cnt[idx];
    sb[t] = s;
    __syncthreads();
    for (int off = 128; off > 0; off >>= 1) {
        if (t < off) sb[t] += sb[t + off];
        __syncthreads();
    }
    if (t == 0) g_blocksum[b] = sb[0];
}

__global__ void __launch_bounds__(128) scan_p2() {
    __shared__ int sb[128];
    int t = threadIdx.x;
    int v = g_blocksum[t];
    sb[t] = v;
    __syncthreads();
    for (int off = 1; off < 128; off <<= 1) {
        int u = (t >= off) ? sb[t - off] : 0;
        __syncthreads();
        sb[t] += u;
        __syncthreads();
    }
    g_blocksum[t] = sb[t] - v;   // exclusive
}

__global__ void __launch_bounds__(256) scan_p3() {
    __shared__ int sb[256];
    __shared__ int s_off;
    int b = blockIdx.x, t = threadIdx.x;
    int base = b * SCAN_CH;
    int end = min(base + SCAN_CH, NN);
    if (t == 0) s_off = g_blocksum[b];
    __syncthreads();
    for (int tile = base; tile < end; tile += 256) {
        int idx = tile + t;
        int c = (idx < end) ? g_cnt[idx] : 0;
        sb[t] = c;
        __syncthreads();
        for (int off = 1; off < 256; off <<= 1) {
            int u = (t >= off) ? sb[t - off] : 0;
            __syncthreads();
            sb[t] += u;
            __syncthreads();
        }
        int incl = sb[t];
        int excl = incl - c;
        if (idx < end) {
            int r = s_off + excl;
            g_row[idx] = r;
            g_cur[idx] = r;
            g_invdeg[idx] = 1.0f / fmaxf((float)c, 1.0f);
        }
        __syncthreads();
        if (t == 255) s_off += sb[255];
        __syncthreads();
    }
}

// ---------------- fill CSR src lists ----------------
__global__ void __launch_bounds__(256) fill_csr(const void* __restrict__ ei) {
    int e = blockIdx.x * blockDim.x + threadIdx.x;
    if (e >= NE) return;
    int dst = getidx(ei, NE + e);
    int src = getidx(ei, e);
    int pos = atomicAdd(&g_cur[dst], 1);
    g_srcs[pos] = src;
}

// ---------------- gather-mean layer 1 (64 ch) ----------------
__global__ void __launch_bounds__(256) gather1(const float4* __restrict__ x4) {
    unsigned t = blockIdx.x * blockDim.x + threadIdx.x;
    unsigned n = t >> 4, q = t & 15;
    if (n >= NN) return;
    int start = g_row[n];
    int cnt = g_cnt[n];
    float inv = g_invdeg[n];
    float4 acc = make_float4(0.f, 0.f, 0.f, 0.f);
    for (int j = 0; j < cnt; j++) {
        int s = g_srcs[start + j];
        float4 v = x4[(size_t)s * 16 + q];
        acc.x += v.x; acc.y += v.y; acc.z += v.z; acc.w += v.w;
    }
    acc.x *= inv; acc.y *= inv; acc.z *= inv; acc.w *= inv;
    ((float4*)g_agg1)[(size_t)n * 16 + q] = acc;
}

// ---------------- gather-mean layer 2 (128 ch) ----------------
__global__ void __launch_bounds__(256) gather2() {
    unsigned t = blockIdx.x * blockDim.x + threadIdx.x;
    unsigned n = t >> 5, q = t & 31;
    if (n >= NN) return;
    int start = g_row[n];
    int cnt = g_cnt[n];
    float inv = g_invdeg[n];
    const float4* h4 = (const float4*)g_h1;
    float4 acc = make_float4(0.f, 0.f, 0.f, 0.f);
    for (int j = 0; j < cnt; j++) {
        int s = g_srcs[start + j];
        float4 v = h4[(size_t)s * 32 + q];
        acc.x += v.x; acc.y += v.y; acc.z += v.z; acc.w += v.w;
    }
    acc.x *= inv; acc.y *= inv; acc.z *= inv; acc.w *= inv;
    ((float4*)g_agg2)[(size_t)n * 32 + q] = acc;
}

// ---------------- tensor-core fused SAGE GEMM (3xTF32) ----------------
// out[n, c] = relu( agg[n] @ W0^T + feat[n] @ W1^T + bias )   (agg pre-normalized)
// Block tile: 128 nodes x 128 ch, 256 threads = 8 warps (4 M x 2 N).
// Warp tile: 32 x 64 -> 2 m16-tiles x 8 n8-tiles of m16n8k8.
// smem layout stride 20 floats: verified conflict-free for fragment loads.
template <int K, bool DO_POOL>
__device__ __forceinline__ void tc_gemm_body(
    const float* __restrict__ agg, const float* __restrict__ feat,
    const float* __restrict__ W0, const float* __restrict__ W1,
    const float* __restrict__ bias, float* __restrict__ out,
    const void* __restrict__ batch) {
    constexpr int KH = K / 2;
    __shared__ float As[128][20];   // [node][k]  (16 k per tile)
    __shared__ float Bs[128][20];   // [outch][k]

    int tid = threadIdx.x;
    int lane = tid & 31, wid = tid >> 5;
    int warpM = wid & 3, warpN = wid >> 2;
    int g = lane >> 2, c = lane & 3;
    int m0 = blockIdx.x * 128;

    int lrow = tid >> 1;             // 0..127
    int lhalf = (tid & 1) * 8;       // 0 or 8

    float acc[2][8][4];
#pragma unroll
    for (int mt = 0; mt < 2; mt++)
#pragma unroll
        for (int nt = 0; nt < 8; nt++)
#pragma unroll
            for (int i = 0; i < 4; i++) acc[mt][nt][i] = 0.f;

    int node_l = m0 + lrow;
    bool av = node_l < NN;

    for (int kk = 0; kk < K; kk += 16) {
        // ---- load A tile: 128 nodes x 16 k ----
        {
            int kg = kk + lhalf;     // uniform per thread; tile entirely agg or feat (KH % 16 == 0)
            float4 v0 = make_float4(0.f, 0.f, 0.f, 0.f);
            float4 v1 = make_float4(0.f, 0.f, 0.f, 0.f);
            if (av) {
                const float* base = (kg < KH) ? (agg + (size_t)node_l * KH + kg)
                                              : (feat + (size_t)node_l * KH + (kg - KH));
                v0 = *(const float4*)base;
                v1 = *(const float4*)(base + 4);
            }
            *(float4*)&As[lrow][lhalf] = v0;
            *(float4*)&As[lrow][lhalf + 4] = v1;
        }
        // ---- load B tile: 128 outch x 16 k, from row-major W [HID][KH] ----
        {
            int kg = kk + lhalf;
            const float* wb = (kg < KH) ? (W0 + (size_t)lrow * KH + kg)
                                        : (W1 + (size_t)lrow * KH + (kg - KH));
            *(float4*)&Bs[lrow][lhalf] = *(const float4*)wb;
            *(float4*)&Bs[lrow][lhalf + 4] = *(const float4*)(wb + 4);
        }
        __syncthreads();

#pragma unroll
        for (int k8 = 0; k8 < 16; k8 += 8) {
            // A fragments (hi/lo) for both m-tiles
            unsigned ah[2][4], al[2][4];
#pragma unroll
            for (int mt = 0; mt < 2; mt++) {
                int rb = warpM * 32 + mt * 16;
                float a0 = As[rb + g][k8 + c];
                float a1 = As[rb + g + 8][k8 + c];
                float a2 = As[rb + g][k8 + c + 4];
                float a3 = As[rb + g + 8][k8 + c + 4];
                ah[mt][0] = f2tf(a0); al[mt][0] = f2tf(a0 - __uint_as_float(ah[mt][0]));
                ah[mt][1] = f2tf(a1); al[mt][1] = f2tf(a1 - __uint_as_float(ah[mt][1]));
                ah[mt][2] = f2tf(a2); al[mt][2] = f2tf(a2 - __uint_as_float(ah[mt][2]));
                ah[mt][3] = f2tf(a3); al[mt][3] = f2tf(a3 - __uint_as_float(ah[mt][3]));
            }
#pragma unroll
            for (int nt = 0; nt < 8; nt++) {
                int nb = warpN * 64 + nt * 8;
                float b0 = Bs[nb + g][k8 + c];
                float b1 = Bs[nb + g][k8 + c + 4];
                unsigned bh[2], bl[2];
                bh[0] = f2tf(b0); bl[0] = f2tf(b0 - __uint_as_float(bh[0]));
                bh[1] = f2tf(b1); bl[1] = f2tf(b1 - __uint_as_float(bh[1]));
#pragma unroll
                for (int mt = 0; mt < 2; mt++) {
                    mma_tf32(acc[mt][nt], ah[mt], bh);   // hi*hi
                    mma_tf32(acc[mt][nt], ah[mt], bl);   // hi*lo
                    mma_tf32(acc[mt][nt], al[mt], bh);   // lo*hi
                }
            }
        }
        __syncthreads();
    }

    // ---- epilogue: bias + relu, then store or pool ----
#pragma unroll
    for (int mt = 0; mt < 2; mt++) {
        int r0 = m0 + warpM * 32 + mt * 16 + g;
        int r1 = r0 + 8;
#pragma unroll
        for (int nt = 0; nt < 8; nt++) {
            int col = warpN * 64 + nt * 8 + 2 * c;
            float b0 = bias[col], b1 = bias[col + 1];
            float v00 = fmaxf(acc[mt][nt][0] + b0, 0.f);
            float v01 = fmaxf(acc[mt][nt][1] + b1, 0.f);
            float v10 = fmaxf(acc[mt][nt][2] + b0, 0.f);
            float v11 = fmaxf(acc[mt][nt][3] + b1, 0.f);
            if (DO_POOL) {
                if (r0 < NN) {
                    float* p = g_pooled + (size_t)getidx(batch, r0) * HID + col;
                    atomicAdd(p, v00);
                    atomicAdd(p + 1, v01);
                }
                if (r1 < NN) {
                    float* p = g_pooled + (size_t)getidx(batch, r1) * HID + col;
                    atomicAdd(p, v10);
                    atomicAdd(p + 1, v11);
                }
            } else {
                if (r0 < NN) *(float2*)(out + (size_t)r0 * HID + col) = make_float2(v00, v01);
                if (r1 < NN) *(float2*)(out + (size_t)r1 * HID + col) = make_float2(v10, v11);
            }
        }
    }
}

__global__ void __launch_bounds__(256) tc_gemm_l1(
    const float* __restrict__ x, const float* __restrict__ W0,
    const float* __restrict__ W1, const float* __restrict__ bias) {
    tc_gemm_body<2 * IN_CH, false>(g_agg1, x, W0, W1, bias, g_h1, nullptr);
}

__global__ void __launch_bounds__(256) tc_gemm_l2(
    const float* __restrict__ W0, const float* __restrict__ W1,
    const float* __restrict__ bias, const void* __restrict__ batch) {
    tc_gemm_body<2 * HID, true>(g_agg2, g_h1, W0, W1, bias, nullptr, batch);
}

// ---------------- finalize: per-graph mean, Wout, log_softmax ----------------
__global__ void __launch_bounds__(256) finalize(const void* __restrict__ batch,
                                                const float* __restrict__ Wout,
                                                const float* __restrict__ bout,
                                                float* __restrict__ outp) {
    int g = threadIdx.x;
    auto lower_bound = [&](int v) {
        int lo = 0, hi = NN;
        while (lo < hi) {
            int mid = (lo + hi) >> 1;
            if (getidx(batch, mid) < v) lo = mid + 1; else hi = mid;
        }
        return lo;
    };
    int cnt = lower_bound(g + 1) - lower_bound(g);
    float inv = 1.0f / fmaxf((float)cnt, 1.0f);
    float l0 = bout[0], l1 = bout[1];
    for (int c = 0; c < HID; c++) {
        float p = g_pooled[(size_t)g * HID + c] * inv;
        l0 += p * Wout[c];
        l1 += p * Wout[HID + c];
    }
    float m = fmaxf(l0, l1);
    float lse = m + logf(expf(l0 - m) + expf(l1 - m));
    outp[g * 2 + 0] = l0 - lse;
    outp[g * 2 + 1] = l1 - lse;
}

// ---------------- launch ----------------
extern "C" void kernel_launch(void* const* d_in, const int* in_sizes, int n_in,
                              void* d_out, int out_size) {
    const float* x = (const float*)d_in[0];
    const void* ei = d_in[1];
    const void* batch = d_in[2];
    const float* Wl1 = (const float*)d_in[3];
    const float* bl1 = (const float*)d_in[4];
    const float* Wr1 = (const float*)d_in[5];
    const float* Wl2 = (const float*)d_in[6];
    const float* bl2 = (const float*)d_in[7];
    const float* Wr2 = (const float*)d_in[8];
    const float* Wout = (const float*)d_in[9];
    const float* bout = (const float*)d_in[10];
    float* out = (float*)d_out;

    int eb = (NE + 255) / 256;
    int gemm_blocks = (NN + 127) / 128;

    probe_dtype<<<1, 32>>>((const unsigned long long*)ei);
    zero_small<<<256, 256>>>();
    hist<<<eb, 256>>>(ei);
    scan_p1<<<SCAN_BLOCKS, 256>>>();
    scan_p2<<<1, 128>>>();
    scan_p3<<<SCAN_BLOCKS, 256>>>();
    fill_csr<<<eb, 256>>>(ei);

    gather1<<<(NN * 16 + 255) / 256, 256>>>((const float4*)x);
    tc_gemm_l1<<<gemm_blocks, 256>>>(x, Wl1, Wr1, bl1);
    gather2<<<(NN * 32 + 255) / 256, 256>>>();
    tc_gemm_l2<<<gemm_blocks, 256>>>(Wl2, Wr2, bl2, batch);
    finalize<<<1, 256>>>(batch, Wout, bout, out);
}